// round 2
// baseline (speedup 1.0000x reference)
#include <cuda_runtime.h>
#include <cuda_bf16.h>

// Problem constants
#define BB   16
#define NN   1029
#define HH   16
#define HD   64
#define DD   1024
#define MM   (BB * NN)          // 16464
#define PREFIX 5                // N - NP
#define TOTAL  (MM * DD)        // 16859136

// Scratch (allocation-free rule: use __device__ globals)
__device__ float g_Y  [TOTAL];
__device__ float g_Q  [TOTAL];
__device__ float g_K  [TOTAL];
__device__ float g_V  [TOTAL];
__device__ float g_CTX[TOTAL];

// ---------------------------------------------------------------------------
// SGEMM NT: C[m,n] = sum_k A[m,k] * W[n,k] + bias[n]
// A: [M,1024] row-major, W: [1024,1024] row-major (both K-contiguous)
// 128x128 tile, k-step 8, 256 threads, 8x8 micro-tile per thread.
// ---------------------------------------------------------------------------
__global__ __launch_bounds__(256) void sgemm_nt(
    const float* __restrict__ A, const float* __restrict__ W,
    const float* __restrict__ bias, float* __restrict__ C, int M)
{
    __shared__ float As[8][128];
    __shared__ float Bs[8][128];

    const int tid  = threadIdx.x;
    const int row0 = blockIdx.y * 128;
    const int col0 = blockIdx.x * 128;
    const int tx = tid & 15;        // 0..15
    const int ty = tid >> 4;        // 0..15

    const int lr = tid >> 1;        // 0..127 : tile row loaded by this thread
    const int lc = (tid & 1) * 4;   // 0 or 4 : k offset within 8-chunk

    const bool arow_ok = (row0 + lr) < M;
    const float* Ag = A + (long long)(row0 + lr) * DD + lc;
    const float* Wg = W + (long long)(col0 + lr) * DD + lc;

    float acc[8][8];
    #pragma unroll
    for (int i = 0; i < 8; i++)
        #pragma unroll
        for (int j = 0; j < 8; j++) acc[i][j] = 0.f;

    for (int k0 = 0; k0 < DD; k0 += 8) {
        float4 av = arow_ok ? *(const float4*)(Ag + k0) : make_float4(0.f,0.f,0.f,0.f);
        float4 wv = *(const float4*)(Wg + k0);
        __syncthreads();
        As[lc+0][lr] = av.x; As[lc+1][lr] = av.y; As[lc+2][lr] = av.z; As[lc+3][lr] = av.w;
        Bs[lc+0][lr] = wv.x; Bs[lc+1][lr] = wv.y; Bs[lc+2][lr] = wv.z; Bs[lc+3][lr] = wv.w;
        __syncthreads();

        #pragma unroll
        for (int kk = 0; kk < 8; kk++) {
            float4 a0 = *(const float4*)&As[kk][ty * 4];
            float4 a1 = *(const float4*)&As[kk][64 + ty * 4];
            float4 b0 = *(const float4*)&Bs[kk][tx * 4];
            float4 b1 = *(const float4*)&Bs[kk][64 + tx * 4];
            float a[8] = {a0.x,a0.y,a0.z,a0.w, a1.x,a1.y,a1.z,a1.w};
            float b[8] = {b0.x,b0.y,b0.z,b0.w, b1.x,b1.y,b1.z,b1.w};
            #pragma unroll
            for (int i = 0; i < 8; i++)
                #pragma unroll
                for (int j = 0; j < 8; j++)
                    acc[i][j] += a[i] * b[j];
        }
    }

    // epilogue: bias + store (vectorized, row-guarded)
    #pragma unroll
    for (int i = 0; i < 8; i++) {
        int r = row0 + ((i < 4) ? (ty * 4 + i) : (64 + ty * 4 + i - 4));
        if (r >= M) continue;
        int c0 = col0 + tx * 4;
        int c1 = col0 + 64 + tx * 4;
        float4 v0, v1;
        v0.x = acc[i][0] + bias[c0+0]; v0.y = acc[i][1] + bias[c0+1];
        v0.z = acc[i][2] + bias[c0+2]; v0.w = acc[i][3] + bias[c0+3];
        v1.x = acc[i][4] + bias[c1+0]; v1.y = acc[i][5] + bias[c1+1];
        v1.z = acc[i][6] + bias[c1+2]; v1.w = acc[i][7] + bias[c1+3];
        *(float4*)(C + (long long)r * DD + c0) = v0;
        *(float4*)(C + (long long)r * DD + c1) = v1;
    }
}

// ---------------------------------------------------------------------------
// Reshape [B,N,H,HD] -> [B,H,N,HD] with optional RoPE on tokens >= PREFIX
// out = x*cos + rotate_half(x)*sin, rotate_half: (-x2, x1) over HD halves
// ---------------------------------------------------------------------------
__global__ void reshape_rope(
    const float* __restrict__ Y, const float* __restrict__ sinp,
    const float* __restrict__ cosp, float* __restrict__ OUT, int do_rope)
{
    long long idx = (long long)blockIdx.x * blockDim.x + threadIdx.x;
    if (idx >= TOTAL) return;
    int m = (int)(idx >> 10);       // / 1024
    int n = (int)(idx & 1023);
    int b = m / NN;
    int t = m - b * NN;
    int h = n >> 6;
    int d = n & 63;

    float v = Y[idx];
    if (do_rope && t >= PREFIX) {
        int pos = t - PREFIX;
        float c = cosp[pos * HD + d];
        float s = sinp[pos * HD + d];
        float other = (d < 32) ? -Y[idx + 32] : Y[idx - 32];
        v = v * c + other * s;
    }
    long long o = (((long long)(b * HH + h)) * NN + t) * HD + d;
    OUT[o] = v;
}

// ---------------------------------------------------------------------------
// Flash attention (fp32, thread-per-query-row, online softmax)
// Q,K,V: [B,H,N,HD].  CTX written as [B,N,H*HD] (ready for O projection).
// Block: 128 threads = 128 query rows. KV tiles of 64 in smem.
// ---------------------------------------------------------------------------
__global__ __launch_bounds__(128) void flash_attn(
    const float* __restrict__ Q, const float* __restrict__ Kt,
    const float* __restrict__ V, float* __restrict__ CTX)
{
    const int q0 = blockIdx.x * 128;
    const int h  = blockIdx.y;
    const int b  = blockIdx.z;
    const long long base = ((long long)(b * HH + h)) * NN * HD;
    const int tid = threadIdx.x;
    const int r   = q0 + tid;
    const bool valid = r < NN;

    __shared__ float4 Ks[64][16];
    __shared__ float4 Vs[64][16];

    float4 q[16];
    if (valid) {
        const float4* qp = (const float4*)(Q + base + (long long)r * HD);
        #pragma unroll
        for (int i = 0; i < 16; i++) {
            q[i] = qp[i];
            q[i].x *= 0.125f; q[i].y *= 0.125f; q[i].z *= 0.125f; q[i].w *= 0.125f;
        }
    } else {
        #pragma unroll
        for (int i = 0; i < 16; i++) q[i] = make_float4(0.f,0.f,0.f,0.f);
    }

    float m = -1e30f, l = 0.f;
    float4 acc[16];
    #pragma unroll
    for (int i = 0; i < 16; i++) acc[i] = make_float4(0.f,0.f,0.f,0.f);

    for (int k0 = 0; k0 < NN; k0 += 64) {
        const int nkv = min(64, NN - k0);
        __syncthreads();
        #pragma unroll
        for (int i = 0; i < 8; i++) {
            int flat = tid + i * 128;      // 0..1023
            int j = flat >> 4, c = flat & 15;
            if (j < nkv) {
                Ks[j][c] = *(const float4*)(Kt + base + (long long)(k0 + j) * HD + c * 4);
                Vs[j][c] = *(const float4*)(V  + base + (long long)(k0 + j) * HD + c * 4);
            } else {
                Ks[j][c] = make_float4(0.f,0.f,0.f,0.f);
                Vs[j][c] = make_float4(0.f,0.f,0.f,0.f);
            }
        }
        __syncthreads();

        #pragma unroll
        for (int half = 0; half < 2; half++) {
            const int jb = half * 32;
            if (jb >= nkv) break;
            float s[32];
            #pragma unroll
            for (int jj = 0; jj < 32; jj++) {
                const float4* krow = Ks[jb + jj];
                float sum = 0.f;
                #pragma unroll
                for (int c = 0; c < 16; c++) {
                    float4 k4 = krow[c];
                    sum += q[c].x*k4.x + q[c].y*k4.y + q[c].z*k4.z + q[c].w*k4.w;
                }
                s[jj] = (k0 + jb + jj < NN) ? sum : -1e30f;
            }
            float mn = m;
            #pragma unroll
            for (int jj = 0; jj < 32; jj++) mn = fmaxf(mn, s[jj]);
            float scale = __expf(m - mn);
            m = mn;
            l *= scale;
            #pragma unroll
            for (int i = 0; i < 16; i++) {
                acc[i].x *= scale; acc[i].y *= scale; acc[i].z *= scale; acc[i].w *= scale;
            }
            #pragma unroll
            for (int jj = 0; jj < 32; jj++) {
                float p = __expf(s[jj] - m);
                l += p;
                const float4* vrow = Vs[jb + jj];
                #pragma unroll
                for (int c = 0; c < 16; c++) {
                    float4 v4 = vrow[c];
                    acc[c].x += p * v4.x; acc[c].y += p * v4.y;
                    acc[c].z += p * v4.z; acc[c].w += p * v4.w;
                }
            }
        }
    }

    if (valid) {
        float inv = 1.f / l;
        float4* op = (float4*)(CTX + ((long long)b * NN + r) * DD + h * HD);
        #pragma unroll
        for (int c = 0; c < 16; c++) {
            float4 o;
            o.x = acc[c].x * inv; o.y = acc[c].y * inv;
            o.z = acc[c].z * inv; o.w = acc[c].w * inv;
            op[c] = o;
        }
    }
}

// ---------------------------------------------------------------------------
extern "C" void kernel_launch(void* const* d_in, const int* in_sizes, int n_in,
                              void* d_out, int out_size)
{
    const float* X    = (const float*)d_in[0];
    const float* sinp = (const float*)d_in[1];
    const float* cosp = (const float*)d_in[2];
    const float* Wq   = (const float*)d_in[3];
    const float* bq   = (const float*)d_in[4];
    const float* Wk   = (const float*)d_in[5];
    const float* bk   = (const float*)d_in[6];
    const float* Wv   = (const float*)d_in[7];
    const float* bv   = (const float*)d_in[8];
    const float* Wo   = (const float*)d_in[9];
    const float* bo   = (const float*)d_in[10];
    float* OUT = (float*)d_out;

    float *Y, *Qb, *Kb, *Vb, *CTX;
    cudaGetSymbolAddress((void**)&Y,   g_Y);
    cudaGetSymbolAddress((void**)&Qb,  g_Q);
    cudaGetSymbolAddress((void**)&Kb,  g_K);
    cudaGetSymbolAddress((void**)&Vb,  g_V);
    cudaGetSymbolAddress((void**)&CTX, g_CTX);

    dim3 ggrid(DD / 128, (MM + 127) / 128);   // (8, 129)
    dim3 gblk(256);
    int rblocks = (TOTAL + 255) / 256;

    // Q projection + rope
    sgemm_nt<<<ggrid, gblk>>>(X, Wq, bq, Y, MM);
    reshape_rope<<<rblocks, 256>>>(Y, sinp, cosp, Qb, 1);
    // K projection + rope
    sgemm_nt<<<ggrid, gblk>>>(X, Wk, bk, Y, MM);
    reshape_rope<<<rblocks, 256>>>(Y, sinp, cosp, Kb, 1);
    // V projection (no rope)
    sgemm_nt<<<ggrid, gblk>>>(X, Wv, bv, Y, MM);
    reshape_rope<<<rblocks, 256>>>(Y, sinp, cosp, Vb, 0);

    // attention
    dim3 agrid((NN + 127) / 128, HH, BB);     // (9,16,16)
    flash_attn<<<agrid, 128>>>(Qb, Kb, Vb, CTX);

    // output projection straight into d_out
    sgemm_nt<<<ggrid, gblk>>>(CTX, Wo, bo, OUT, MM);
}

// round 3
// speedup vs baseline: 1.3477x; 1.3477x over previous
#include <cuda_runtime.h>
#include <cuda_bf16.h>

// Problem constants
#define BB   16
#define NN   1029
#define HH   16
#define HD   64
#define DD   1024
#define MM   (BB * NN)          // 16464
#define PREFIX 5                // N - NP
#define TOTAL  (MM * DD)        // 16859136

// Scratch (allocation-free rule: use __device__ globals)
__device__ float g_Y  [TOTAL];
__device__ float g_Q  [TOTAL];
__device__ float g_K  [TOTAL];
__device__ float g_V  [TOTAL];
__device__ float g_CTX[TOTAL];

__device__ __forceinline__ unsigned f2tf(float x) {
    unsigned r;
    asm("cvt.rna.tf32.f32 %0, %1;" : "=r"(r) : "f"(x));
    return r;
}

__device__ __forceinline__ void mma_tf32(
    float& c0, float& c1, float& c2, float& c3,
    unsigned a0, unsigned a1, unsigned a2, unsigned a3,
    unsigned b0, unsigned b1)
{
    asm volatile(
        "mma.sync.aligned.m16n8k8.row.col.f32.tf32.tf32.f32 "
        "{%0,%1,%2,%3}, {%4,%5,%6,%7}, {%8,%9}, {%0,%1,%2,%3};\n"
        : "+f"(c0), "+f"(c1), "+f"(c2), "+f"(c3)
        : "r"(a0), "r"(a1), "r"(a2), "r"(a3), "r"(b0), "r"(b1));
}

// ---------------------------------------------------------------------------
// TF32 tensor-core GEMM NT: C[m,n] = sum_k A[m,k] * W[n,k] + bias[n]
// 128x128 block tile, k-chunk 32, 256 threads (8 warps), warp tile 64x32.
// ---------------------------------------------------------------------------
#define KPAD 36
__global__ __launch_bounds__(256) void gemm_tf32(
    const float* __restrict__ A, const float* __restrict__ W,
    const float* __restrict__ bias, float* __restrict__ C, int M)
{
    __shared__ unsigned As[128 * KPAD];
    __shared__ unsigned Ws[128 * KPAD];

    const int tid  = threadIdx.x;
    const int warp = tid >> 5;
    const int lane = tid & 31;
    const int g    = lane >> 2;   // 0..7
    const int q    = lane & 3;    // 0..3
    const int wm   = warp >> 2;   // 0..1 -> 64-row group
    const int wn   = warp & 3;    // 0..3 -> 32-col group
    const int row0 = blockIdx.y * 128;
    const int col0 = blockIdx.x * 128;

    float acc[4][4][4];
    #pragma unroll
    for (int mt = 0; mt < 4; mt++)
        #pragma unroll
        for (int nt = 0; nt < 4; nt++)
            #pragma unroll
            for (int i = 0; i < 4; i++) acc[mt][nt][i] = 0.f;

    // loader mapping: 1024 float4s per tile (128 rows x 8 quads), 4 per thread
    int lrow[4], lk[4];
    #pragma unroll
    for (int j = 0; j < 4; j++) {
        int idx = tid + j * 256;
        lrow[j] = idx >> 3;
        lk[j]   = (idx & 7) * 4;
    }

    const float4 z4 = make_float4(0.f, 0.f, 0.f, 0.f);
    float4 pa[4], pw[4];
    #pragma unroll
    for (int j = 0; j < 4; j++) {
        int r = row0 + lrow[j];
        pa[j] = (r < M) ? *(const float4*)(A + (long long)r * DD + lk[j]) : z4;
        pw[j] = *(const float4*)(W + (long long)(col0 + lrow[j]) * DD + lk[j]);
    }

    for (int chunk = 0; chunk < DD / 32; chunk++) {
        #pragma unroll
        for (int j = 0; j < 4; j++) {
            unsigned* as = &As[lrow[j] * KPAD + lk[j]];
            as[0] = f2tf(pa[j].x); as[1] = f2tf(pa[j].y);
            as[2] = f2tf(pa[j].z); as[3] = f2tf(pa[j].w);
            unsigned* ws = &Ws[lrow[j] * KPAD + lk[j]];
            ws[0] = f2tf(pw[j].x); ws[1] = f2tf(pw[j].y);
            ws[2] = f2tf(pw[j].z); ws[3] = f2tf(pw[j].w);
        }
        __syncthreads();

        if (chunk + 1 < DD / 32) {
            int kb = (chunk + 1) * 32;
            #pragma unroll
            for (int j = 0; j < 4; j++) {
                int r = row0 + lrow[j];
                pa[j] = (r < M) ? *(const float4*)(A + (long long)r * DD + kb + lk[j]) : z4;
                pw[j] = *(const float4*)(W + (long long)(col0 + lrow[j]) * DD + kb + lk[j]);
            }
        }

        #pragma unroll
        for (int ks = 0; ks < 4; ks++) {
            const int kc = ks * 8 + q;
            unsigned af[4][4], bf[4][2];
            #pragma unroll
            for (int mt = 0; mt < 4; mt++) {
                int base = (wm * 64 + mt * 16 + g) * KPAD + kc;
                af[mt][0] = As[base];
                af[mt][1] = As[base + 8 * KPAD];
                af[mt][2] = As[base + 4];
                af[mt][3] = As[base + 8 * KPAD + 4];
            }
            #pragma unroll
            for (int nt = 0; nt < 4; nt++) {
                int base = (wn * 32 + nt * 8 + g) * KPAD + kc;
                bf[nt][0] = Ws[base];
                bf[nt][1] = Ws[base + 4];
            }
            #pragma unroll
            for (int mt = 0; mt < 4; mt++)
                #pragma unroll
                for (int nt = 0; nt < 4; nt++)
                    mma_tf32(acc[mt][nt][0], acc[mt][nt][1],
                             acc[mt][nt][2], acc[mt][nt][3],
                             af[mt][0], af[mt][1], af[mt][2], af[mt][3],
                             bf[nt][0], bf[nt][1]);
        }
        __syncthreads();
    }

    // epilogue: bias + store
    #pragma unroll
    for (int mt = 0; mt < 4; mt++) {
        int r0 = row0 + wm * 64 + mt * 16 + g;
        int r1 = r0 + 8;
        #pragma unroll
        for (int nt = 0; nt < 4; nt++) {
            int c = col0 + wn * 32 + nt * 8 + 2 * q;
            float bx = bias[c], by = bias[c + 1];
            if (r0 < M) {
                float2 v = make_float2(acc[mt][nt][0] + bx, acc[mt][nt][1] + by);
                *(float2*)(C + (long long)r0 * DD + c) = v;
            }
            if (r1 < M) {
                float2 v = make_float2(acc[mt][nt][2] + bx, acc[mt][nt][3] + by);
                *(float2*)(C + (long long)r1 * DD + c) = v;
            }
        }
    }
}

// ---------------------------------------------------------------------------
// Reshape [B,N,H,HD] -> [B,H,N,HD] with optional RoPE on tokens >= PREFIX
// ---------------------------------------------------------------------------
__global__ void reshape_rope(
    const float* __restrict__ Y, const float* __restrict__ sinp,
    const float* __restrict__ cosp, float* __restrict__ OUT, int do_rope)
{
    long long idx = (long long)blockIdx.x * blockDim.x + threadIdx.x;
    if (idx >= TOTAL) return;
    int m = (int)(idx >> 10);       // / 1024
    int n = (int)(idx & 1023);
    int b = m / NN;
    int t = m - b * NN;
    int h = n >> 6;
    int d = n & 63;

    float v = Y[idx];
    if (do_rope && t >= PREFIX) {
        int pos = t - PREFIX;
        float c = cosp[pos * HD + d];
        float s = sinp[pos * HD + d];
        float other = (d < 32) ? -Y[idx + 32] : Y[idx - 32];
        v = v * c + other * s;
    }
    long long o = (((long long)(b * HH + h)) * NN + t) * HD + d;
    OUT[o] = v;
}

// ---------------------------------------------------------------------------
// Flash attention (fp32, thread-per-query-row, online softmax)
// ---------------------------------------------------------------------------
__global__ __launch_bounds__(128) void flash_attn(
    const float* __restrict__ Q, const float* __restrict__ Kt,
    const float* __restrict__ V, float* __restrict__ CTX)
{
    const int q0 = blockIdx.x * 128;
    const int h  = blockIdx.y;
    const int b  = blockIdx.z;
    const long long base = ((long long)(b * HH + h)) * NN * HD;
    const int tid = threadIdx.x;
    const int r   = q0 + tid;
    const bool valid = r < NN;

    __shared__ float4 Ks[64][16];
    __shared__ float4 Vs[64][16];

    float4 q[16];
    if (valid) {
        const float4* qp = (const float4*)(Q + base + (long long)r * HD);
        #pragma unroll
        for (int i = 0; i < 16; i++) {
            q[i] = qp[i];
            q[i].x *= 0.125f; q[i].y *= 0.125f; q[i].z *= 0.125f; q[i].w *= 0.125f;
        }
    } else {
        #pragma unroll
        for (int i = 0; i < 16; i++) q[i] = make_float4(0.f,0.f,0.f,0.f);
    }

    float m = -1e30f, l = 0.f;
    float4 acc[16];
    #pragma unroll
    for (int i = 0; i < 16; i++) acc[i] = make_float4(0.f,0.f,0.f,0.f);

    for (int k0 = 0; k0 < NN; k0 += 64) {
        const int nkv = min(64, NN - k0);
        __syncthreads();
        #pragma unroll
        for (int i = 0; i < 8; i++) {
            int flat = tid + i * 128;      // 0..1023
            int j = flat >> 4, c = flat & 15;
            if (j < nkv) {
                Ks[j][c] = *(const float4*)(Kt + base + (long long)(k0 + j) * HD + c * 4);
                Vs[j][c] = *(const float4*)(V  + base + (long long)(k0 + j) * HD + c * 4);
            } else {
                Ks[j][c] = make_float4(0.f,0.f,0.f,0.f);
                Vs[j][c] = make_float4(0.f,0.f,0.f,0.f);
            }
        }
        __syncthreads();

        #pragma unroll
        for (int half = 0; half < 2; half++) {
            const int jb = half * 32;
            if (jb >= nkv) break;
            float s[32];
            #pragma unroll
            for (int jj = 0; jj < 32; jj++) {
                const float4* krow = Ks[jb + jj];
                float sum = 0.f;
                #pragma unroll
                for (int c = 0; c < 16; c++) {
                    float4 k4 = krow[c];
                    sum += q[c].x*k4.x + q[c].y*k4.y + q[c].z*k4.z + q[c].w*k4.w;
                }
                s[jj] = (k0 + jb + jj < NN) ? sum : -1e30f;
            }
            float mn = m;
            #pragma unroll
            for (int jj = 0; jj < 32; jj++) mn = fmaxf(mn, s[jj]);
            float scale = __expf(m - mn);
            m = mn;
            l *= scale;
            #pragma unroll
            for (int i = 0; i < 16; i++) {
                acc[i].x *= scale; acc[i].y *= scale; acc[i].z *= scale; acc[i].w *= scale;
            }
            #pragma unroll
            for (int jj = 0; jj < 32; jj++) {
                float p = __expf(s[jj] - m);
                l += p;
                const float4* vrow = Vs[jb + jj];
                #pragma unroll
                for (int c = 0; c < 16; c++) {
                    float4 v4 = vrow[c];
                    acc[c].x += p * v4.x; acc[c].y += p * v4.y;
                    acc[c].z += p * v4.z; acc[c].w += p * v4.w;
                }
            }
        }
    }

    if (valid) {
        float inv = 1.f / l;
        float4* op = (float4*)(CTX + ((long long)b * NN + r) * DD + h * HD);
        #pragma unroll
        for (int c = 0; c < 16; c++) {
            float4 o;
            o.x = acc[c].x * inv; o.y = acc[c].y * inv;
            o.z = acc[c].z * inv; o.w = acc[c].w * inv;
            op[c] = o;
        }
    }
}

// ---------------------------------------------------------------------------
extern "C" void kernel_launch(void* const* d_in, const int* in_sizes, int n_in,
                              void* d_out, int out_size)
{
    const float* X    = (const float*)d_in[0];
    const float* sinp = (const float*)d_in[1];
    const float* cosp = (const float*)d_in[2];
    const float* Wq   = (const float*)d_in[3];
    const float* bq   = (const float*)d_in[4];
    const float* Wk   = (const float*)d_in[5];
    const float* bk   = (const float*)d_in[6];
    const float* Wv   = (const float*)d_in[7];
    const float* bv   = (const float*)d_in[8];
    const float* Wo   = (const float*)d_in[9];
    const float* bo   = (const float*)d_in[10];
    float* OUT = (float*)d_out;

    float *Y, *Qb, *Kb, *Vb, *CTX;
    cudaGetSymbolAddress((void**)&Y,   g_Y);
    cudaGetSymbolAddress((void**)&Qb,  g_Q);
    cudaGetSymbolAddress((void**)&Kb,  g_K);
    cudaGetSymbolAddress((void**)&Vb,  g_V);
    cudaGetSymbolAddress((void**)&CTX, g_CTX);

    dim3 ggrid(DD / 128, (MM + 127) / 128);   // (8, 129)
    dim3 gblk(256);
    int rblocks = (TOTAL + 255) / 256;

    // Q projection + rope
    gemm_tf32<<<ggrid, gblk>>>(X, Wq, bq, Y, MM);
    reshape_rope<<<rblocks, 256>>>(Y, sinp, cosp, Qb, 1);
    // K projection + rope
    gemm_tf32<<<ggrid, gblk>>>(X, Wk, bk, Y, MM);
    reshape_rope<<<rblocks, 256>>>(Y, sinp, cosp, Kb, 1);
    // V projection (no rope)
    gemm_tf32<<<ggrid, gblk>>>(X, Wv, bv, Y, MM);
    reshape_rope<<<rblocks, 256>>>(Y, sinp, cosp, Vb, 0);

    // attention
    dim3 agrid((NN + 127) / 128, HH, BB);     // (9,16,16)
    flash_attn<<<agrid, 128>>>(Qb, Kb, Vb, CTX);

    // output projection straight into d_out
    gemm_tf32<<<ggrid, gblk>>>(CTX, Wo, bo, OUT, MM);
}

// round 4
// speedup vs baseline: 4.5926x; 3.4078x over previous
#include <cuda_runtime.h>
#include <cuda_bf16.h>

// Problem constants
#define BB   16
#define NN   1029
#define HH   16
#define HD   64
#define DD   1024
#define MM   (BB * NN)          // 16464
#define PREFIX 5                // N - NP
#define TOTAL  (MM * DD)        // 16859136

// Scratch (allocation-free rule: use __device__ globals)
__device__ float g_Y  [TOTAL];
__device__ float g_Q  [TOTAL];
__device__ float g_K  [TOTAL];
__device__ float g_V  [TOTAL];
__device__ float g_CTX[TOTAL];

__device__ __forceinline__ unsigned f2tf(float x) {
    unsigned r;
    asm("cvt.rna.tf32.f32 %0, %1;" : "=r"(r) : "f"(x));
    return r;
}

__device__ __forceinline__ void mma_tf32(
    float& c0, float& c1, float& c2, float& c3,
    unsigned a0, unsigned a1, unsigned a2, unsigned a3,
    unsigned b0, unsigned b1)
{
    asm volatile(
        "mma.sync.aligned.m16n8k8.row.col.f32.tf32.tf32.f32 "
        "{%0,%1,%2,%3}, {%4,%5,%6,%7}, {%8,%9}, {%0,%1,%2,%3};\n"
        : "+f"(c0), "+f"(c1), "+f"(c2), "+f"(c3)
        : "r"(a0), "r"(a1), "r"(a2), "r"(a3), "r"(b0), "r"(b1));
}

// ---------------------------------------------------------------------------
// TF32 tensor-core GEMM NT: C[m,n] = sum_k A[m,k] * W[n,k] + bias[n]
// ---------------------------------------------------------------------------
#define KPAD 36
__global__ __launch_bounds__(256) void gemm_tf32(
    const float* __restrict__ A, const float* __restrict__ W,
    const float* __restrict__ bias, float* __restrict__ C, int M)
{
    __shared__ unsigned As[128 * KPAD];
    __shared__ unsigned Ws[128 * KPAD];

    const int tid  = threadIdx.x;
    const int warp = tid >> 5;
    const int lane = tid & 31;
    const int g    = lane >> 2;   // 0..7
    const int q    = lane & 3;    // 0..3
    const int wm   = warp >> 2;   // 0..1
    const int wn   = warp & 3;    // 0..3
    const int row0 = blockIdx.y * 128;
    const int col0 = blockIdx.x * 128;

    float acc[4][4][4];
    #pragma unroll
    for (int mt = 0; mt < 4; mt++)
        #pragma unroll
        for (int nt = 0; nt < 4; nt++)
            #pragma unroll
            for (int i = 0; i < 4; i++) acc[mt][nt][i] = 0.f;

    int lrow[4], lk[4];
    #pragma unroll
    for (int j = 0; j < 4; j++) {
        int idx = tid + j * 256;
        lrow[j] = idx >> 3;
        lk[j]   = (idx & 7) * 4;
    }

    const float4 z4 = make_float4(0.f, 0.f, 0.f, 0.f);
    float4 pa[4], pw[4];
    #pragma unroll
    for (int j = 0; j < 4; j++) {
        int r = row0 + lrow[j];
        pa[j] = (r < M) ? *(const float4*)(A + (long long)r * DD + lk[j]) : z4;
        pw[j] = *(const float4*)(W + (long long)(col0 + lrow[j]) * DD + lk[j]);
    }

    for (int chunk = 0; chunk < DD / 32; chunk++) {
        #pragma unroll
        for (int j = 0; j < 4; j++) {
            unsigned* as = &As[lrow[j] * KPAD + lk[j]];
            as[0] = f2tf(pa[j].x); as[1] = f2tf(pa[j].y);
            as[2] = f2tf(pa[j].z); as[3] = f2tf(pa[j].w);
            unsigned* ws = &Ws[lrow[j] * KPAD + lk[j]];
            ws[0] = f2tf(pw[j].x); ws[1] = f2tf(pw[j].y);
            ws[2] = f2tf(pw[j].z); ws[3] = f2tf(pw[j].w);
        }
        __syncthreads();

        if (chunk + 1 < DD / 32) {
            int kb = (chunk + 1) * 32;
            #pragma unroll
            for (int j = 0; j < 4; j++) {
                int r = row0 + lrow[j];
                pa[j] = (r < M) ? *(const float4*)(A + (long long)r * DD + kb + lk[j]) : z4;
                pw[j] = *(const float4*)(W + (long long)(col0 + lrow[j]) * DD + kb + lk[j]);
            }
        }

        #pragma unroll
        for (int ks = 0; ks < 4; ks++) {
            const int kc = ks * 8 + q;
            unsigned af[4][4], bf[4][2];
            #pragma unroll
            for (int mt = 0; mt < 4; mt++) {
                int base = (wm * 64 + mt * 16 + g) * KPAD + kc;
                af[mt][0] = As[base];
                af[mt][1] = As[base + 8 * KPAD];
                af[mt][2] = As[base + 4];
                af[mt][3] = As[base + 8 * KPAD + 4];
            }
            #pragma unroll
            for (int nt = 0; nt < 4; nt++) {
                int base = (wn * 32 + nt * 8 + g) * KPAD + kc;
                bf[nt][0] = Ws[base];
                bf[nt][1] = Ws[base + 4];
            }
            #pragma unroll
            for (int mt = 0; mt < 4; mt++)
                #pragma unroll
                for (int nt = 0; nt < 4; nt++)
                    mma_tf32(acc[mt][nt][0], acc[mt][nt][1],
                             acc[mt][nt][2], acc[mt][nt][3],
                             af[mt][0], af[mt][1], af[mt][2], af[mt][3],
                             bf[nt][0], bf[nt][1]);
        }
        __syncthreads();
    }

    #pragma unroll
    for (int mt = 0; mt < 4; mt++) {
        int r0 = row0 + wm * 64 + mt * 16 + g;
        int r1 = r0 + 8;
        #pragma unroll
        for (int nt = 0; nt < 4; nt++) {
            int c = col0 + wn * 32 + nt * 8 + 2 * q;
            float bx = bias[c], by = bias[c + 1];
            if (r0 < M) {
                float2 v = make_float2(acc[mt][nt][0] + bx, acc[mt][nt][1] + by);
                *(float2*)(C + (long long)r0 * DD + c) = v;
            }
            if (r1 < M) {
                float2 v = make_float2(acc[mt][nt][2] + bx, acc[mt][nt][3] + by);
                *(float2*)(C + (long long)r1 * DD + c) = v;
            }
        }
    }
}

// ---------------------------------------------------------------------------
// Reshape [B,N,H,HD] -> [B,H,N,HD] with RoPE on tokens >= PREFIX (Q/K only)
// ---------------------------------------------------------------------------
__global__ void reshape_rope(
    const float* __restrict__ Y, const float* __restrict__ sinp,
    const float* __restrict__ cosp, float* __restrict__ OUT)
{
    long long idx = (long long)blockIdx.x * blockDim.x + threadIdx.x;
    if (idx >= TOTAL) return;
    int m = (int)(idx >> 10);
    int n = (int)(idx & 1023);
    int b = m / NN;
    int t = m - b * NN;
    int h = n >> 6;
    int d = n & 63;

    float v = Y[idx];
    if (t >= PREFIX) {
        int pos = t - PREFIX;
        float c = cosp[pos * HD + d];
        float s = sinp[pos * HD + d];
        float other = (d < 32) ? -Y[idx + 32] : Y[idx - 32];
        v = v * c + other * s;
    }
    long long o = (((long long)(b * HH + h)) * NN + t) * HD + d;
    OUT[o] = v;
}

// ---------------------------------------------------------------------------
// Tensor-core flash attention (tf32 mma, online softmax)
// Q,K: [B,H,N,HD].  V: [B,N,H*HD] (raw GEMM output).  CTX: [B,N,H*HD].
// Block: 256 threads (8 warps), 128-query tile, 64-KV tiles.
// QK^T: warp w -> S rows w*16..+15 x 64 kv.   PV: O^T, warp w -> d rows
// (w&3)*16..+15 x query cols (w>>2)*64..+63.  P exchanged via smem.
// ---------------------------------------------------------------------------
#define ST 68
#define FA_SMEM ((384 * ST) * 4 + 256 * 4)

__global__ __launch_bounds__(256) void flash_attn_tc(
    const float* __restrict__ Q, const float* __restrict__ K,
    const float* __restrict__ Vy, float* __restrict__ CTX)
{
    extern __shared__ unsigned sm_u[];
    unsigned* Qs = sm_u;                    // 128 x ST
    unsigned* Ks = Qs + 128 * ST;           // 64 x ST
    unsigned* Vs = Ks + 64 * ST;            // 64 x ST  ([kv][d])
    unsigned* Ps = Vs + 64 * ST;            // 128 x ST (tf32 P / float O stage)
    float* scl  = (float*)(Ps + 128 * ST);  // 128 per-query rescale
    float* linv = scl + 128;                // 128 per-query 1/l

    const int q0 = blockIdx.x * 128;
    const int h  = blockIdx.y;
    const int b  = blockIdx.z;
    const long long baseQ = ((long long)(b * HH + h)) * NN * HD;
    const int tid  = threadIdx.x;
    const int warp = tid >> 5;
    const int lane = tid & 31;
    const int g    = lane >> 2;
    const int q    = lane & 3;
    const int sr0  = warp * 16 + g;       // S-phase rows (queries)
    const int sr1  = sr0 + 8;
    const int d0   = (warp & 3) * 16;     // O-phase d rows
    const int qb   = (warp >> 2) * 64;    // O-phase query cols

    // load Q tile (scaled by HD^-0.5)
    #pragma unroll
    for (int i = 0; i < 8; i++) {
        int idx = tid + i * 256;
        int row = idx >> 4, c4 = (idx & 15) * 4;
        int r = q0 + row;
        float4 v = (r < NN) ? *(const float4*)(Q + baseQ + (long long)r * HD + c4)
                            : make_float4(0.f, 0.f, 0.f, 0.f);
        unsigned* p = &Qs[row * ST + c4];
        p[0] = f2tf(v.x * 0.125f); p[1] = f2tf(v.y * 0.125f);
        p[2] = f2tf(v.z * 0.125f); p[3] = f2tf(v.w * 0.125f);
    }

    float m0 = -1e30f, m1 = -1e30f, l0 = 0.f, l1 = 0.f;
    float oacc[8][4];
    #pragma unroll
    for (int nt = 0; nt < 8; nt++)
        #pragma unroll
        for (int i = 0; i < 4; i++) oacc[nt][i] = 0.f;

    for (int k0 = 0; k0 < NN; k0 += 64) {
        __syncthreads();
        // load K and V tiles
        #pragma unroll
        for (int i = 0; i < 4; i++) {
            int idx = tid + i * 256;
            int j = idx >> 4, c4 = (idx & 15) * 4;
            int kv = k0 + j;
            float4 kvec, vvec;
            if (kv < NN) {
                kvec = *(const float4*)(K + baseQ + (long long)kv * HD + c4);
                vvec = *(const float4*)(Vy + ((long long)(b * NN + kv)) * DD + h * HD + c4);
            } else {
                kvec = make_float4(0.f, 0.f, 0.f, 0.f);
                vvec = kvec;
            }
            unsigned* pk = &Ks[j * ST + c4];
            pk[0] = f2tf(kvec.x); pk[1] = f2tf(kvec.y);
            pk[2] = f2tf(kvec.z); pk[3] = f2tf(kvec.w);
            unsigned* pv = &Vs[j * ST + c4];
            pv[0] = f2tf(vvec.x); pv[1] = f2tf(vvec.y);
            pv[2] = f2tf(vvec.z); pv[3] = f2tf(vvec.w);
        }
        __syncthreads();

        // S = Q @ K^T for this warp's 16 rows
        float sacc[8][4];
        #pragma unroll
        for (int nt = 0; nt < 8; nt++)
            #pragma unroll
            for (int i = 0; i < 4; i++) sacc[nt][i] = 0.f;

        #pragma unroll
        for (int ks = 0; ks < 8; ks++) {
            const int kc = ks * 8 + q;
            unsigned a0 = Qs[sr0 * ST + kc];
            unsigned a1 = Qs[sr1 * ST + kc];
            unsigned a2 = Qs[sr0 * ST + kc + 4];
            unsigned a3 = Qs[sr1 * ST + kc + 4];
            #pragma unroll
            for (int nt = 0; nt < 8; nt++) {
                unsigned b0 = Ks[(nt * 8 + g) * ST + kc];
                unsigned b1 = Ks[(nt * 8 + g) * ST + kc + 4];
                mma_tf32(sacc[nt][0], sacc[nt][1], sacc[nt][2], sacc[nt][3],
                         a0, a1, a2, a3, b0, b1);
            }
        }

        // mask out-of-range kv
        if (k0 + 64 > NN) {
            #pragma unroll
            for (int nt = 0; nt < 8; nt++) {
                int c = k0 + nt * 8 + 2 * q;
                if (c >= NN)     { sacc[nt][0] = -1e30f; sacc[nt][2] = -1e30f; }
                if (c + 1 >= NN) { sacc[nt][1] = -1e30f; sacc[nt][3] = -1e30f; }
            }
        }

        // online softmax (quad-wide rows)
        float t0 = -1e30f, t1 = -1e30f;
        #pragma unroll
        for (int nt = 0; nt < 8; nt++) {
            t0 = fmaxf(t0, fmaxf(sacc[nt][0], sacc[nt][1]));
            t1 = fmaxf(t1, fmaxf(sacc[nt][2], sacc[nt][3]));
        }
        t0 = fmaxf(t0, __shfl_xor_sync(0xffffffffu, t0, 1));
        t0 = fmaxf(t0, __shfl_xor_sync(0xffffffffu, t0, 2));
        t1 = fmaxf(t1, __shfl_xor_sync(0xffffffffu, t1, 1));
        t1 = fmaxf(t1, __shfl_xor_sync(0xffffffffu, t1, 2));
        float mn0 = fmaxf(m0, t0), mn1 = fmaxf(m1, t1);
        float sc0 = __expf(m0 - mn0), sc1 = __expf(m1 - mn1);
        m0 = mn0; m1 = mn1;

        float ls0 = 0.f, ls1 = 0.f;
        #pragma unroll
        for (int nt = 0; nt < 8; nt++) {
            float p0 = __expf(sacc[nt][0] - mn0);
            float p1 = __expf(sacc[nt][1] - mn0);
            float p2 = __expf(sacc[nt][2] - mn1);
            float p3 = __expf(sacc[nt][3] - mn1);
            ls0 += p0 + p1;
            ls1 += p2 + p3;
            uint2 w0 = make_uint2(f2tf(p0), f2tf(p1));
            uint2 w1 = make_uint2(f2tf(p2), f2tf(p3));
            *(uint2*)&Ps[sr0 * ST + nt * 8 + 2 * q] = w0;
            *(uint2*)&Ps[sr1 * ST + nt * 8 + 2 * q] = w1;
        }
        ls0 += __shfl_xor_sync(0xffffffffu, ls0, 1);
        ls0 += __shfl_xor_sync(0xffffffffu, ls0, 2);
        ls1 += __shfl_xor_sync(0xffffffffu, ls1, 1);
        ls1 += __shfl_xor_sync(0xffffffffu, ls1, 2);
        l0 = l0 * sc0 + ls0;
        l1 = l1 * sc1 + ls1;
        if (q == 0) { scl[sr0] = sc0; scl[sr1] = sc1; }
        __syncthreads();

        // rescale O accumulators by per-query factor
        #pragma unroll
        for (int nt = 0; nt < 8; nt++) {
            float s0 = scl[qb + nt * 8 + 2 * q];
            float s1 = scl[qb + nt * 8 + 2 * q + 1];
            oacc[nt][0] *= s0; oacc[nt][1] *= s1;
            oacc[nt][2] *= s0; oacc[nt][3] *= s1;
        }
        // O^T += V^T @ P^T  (A = V [kv][d] as [d x kv], B = P [query][kv])
        #pragma unroll
        for (int ks = 0; ks < 8; ks++) {
            const int kc = ks * 8 + q;
            unsigned a0 = Vs[kc * ST + d0 + g];
            unsigned a1 = Vs[kc * ST + d0 + g + 8];
            unsigned a2 = Vs[(kc + 4) * ST + d0 + g];
            unsigned a3 = Vs[(kc + 4) * ST + d0 + g + 8];
            #pragma unroll
            for (int nt = 0; nt < 8; nt++) {
                unsigned b0 = Ps[(qb + nt * 8 + g) * ST + kc];
                unsigned b1 = Ps[(qb + nt * 8 + g) * ST + kc + 4];
                mma_tf32(oacc[nt][0], oacc[nt][1], oacc[nt][2], oacc[nt][3],
                         a0, a1, a2, a3, b0, b1);
            }
        }
    }

    // final 1/l exchange
    if (q == 0) { linv[sr0] = 1.f / l0; linv[sr1] = 1.f / l1; }
    __syncthreads();

    // stage normalized O (transpose back to [query][d]) in smem
    float* Osm = (float*)Ps;
    #pragma unroll
    for (int nt = 0; nt < 8; nt++) {
        int qc = qb + nt * 8 + 2 * q;
        float i0 = linv[qc], i1 = linv[qc + 1];
        Osm[qc * ST + d0 + g]           = oacc[nt][0] * i0;
        Osm[(qc + 1) * ST + d0 + g]     = oacc[nt][1] * i1;
        Osm[qc * ST + d0 + g + 8]       = oacc[nt][2] * i0;
        Osm[(qc + 1) * ST + d0 + g + 8] = oacc[nt][3] * i1;
    }
    __syncthreads();

    // coalesced output
    #pragma unroll
    for (int i = 0; i < 8; i++) {
        int idx = tid + i * 256;
        int row = idx >> 4, c4 = (idx & 15) * 4;
        int r = q0 + row;
        if (r < NN) {
            float4 v = *(float4*)&Osm[row * ST + c4];
            *(float4*)(CTX + ((long long)(b * NN + r)) * DD + h * HD + c4) = v;
        }
    }
}

// ---------------------------------------------------------------------------
extern "C" void kernel_launch(void* const* d_in, const int* in_sizes, int n_in,
                              void* d_out, int out_size)
{
    const float* X    = (const float*)d_in[0];
    const float* sinp = (const float*)d_in[1];
    const float* cosp = (const float*)d_in[2];
    const float* Wq   = (const float*)d_in[3];
    const float* bq   = (const float*)d_in[4];
    const float* Wk   = (const float*)d_in[5];
    const float* bk   = (const float*)d_in[6];
    const float* Wv   = (const float*)d_in[7];
    const float* bv   = (const float*)d_in[8];
    const float* Wo   = (const float*)d_in[9];
    const float* bo   = (const float*)d_in[10];
    float* OUT = (float*)d_out;

    float *Y, *Qb, *Kb, *Vb, *CTX;
    cudaGetSymbolAddress((void**)&Y,   g_Y);
    cudaGetSymbolAddress((void**)&Qb,  g_Q);
    cudaGetSymbolAddress((void**)&Kb,  g_K);
    cudaGetSymbolAddress((void**)&Vb,  g_V);
    cudaGetSymbolAddress((void**)&CTX, g_CTX);

    cudaFuncSetAttribute(flash_attn_tc,
                         cudaFuncAttributeMaxDynamicSharedMemorySize, FA_SMEM);

    dim3 ggrid(DD / 128, (MM + 127) / 128);
    dim3 gblk(256);
    int rblocks = (TOTAL + 255) / 256;

    // Q projection + rope
    gemm_tf32<<<ggrid, gblk>>>(X, Wq, bq, Y, MM);
    reshape_rope<<<rblocks, 256>>>(Y, sinp, cosp, Qb);
    // K projection + rope
    gemm_tf32<<<ggrid, gblk>>>(X, Wk, bk, Y, MM);
    reshape_rope<<<rblocks, 256>>>(Y, sinp, cosp, Kb);
    // V projection (stays in [B,N,H*HD] layout; attention reads it directly)
    gemm_tf32<<<ggrid, gblk>>>(X, Wv, bv, Vb, MM);

    // tensor-core attention
    dim3 agrid((NN + 127) / 128, HH, BB);   // (9,16,16)
    flash_attn_tc<<<agrid, 256, FA_SMEM>>>(Qb, Kb, Vb, CTX);

    // output projection straight into d_out
    gemm_tf32<<<ggrid, gblk>>>(CTX, Wo, bo, OUT, MM);
}

// round 9
// speedup vs baseline: 4.8165x; 1.0487x over previous
#include <cuda_runtime.h>
#include <cuda_bf16.h>

// Problem constants
#define BB   16
#define NN   1029
#define HH   16
#define HD   64
#define DD   1024
#define MM   (BB * NN)          // 16464
#define PREFIX 5                // N - NP
#define TOTAL  (MM * DD)        // 16859136

// Scratch (allocation-free rule: use __device__ globals)
__device__ float g_Q  [TOTAL];
__device__ float g_K  [TOTAL];
__device__ float g_V  [TOTAL];
__device__ float g_CTX[TOTAL];

__device__ __forceinline__ unsigned f2tf(float x) {
    unsigned r;
    asm("cvt.rna.tf32.f32 %0, %1;" : "=r"(r) : "f"(x));
    return r;
}

__device__ __forceinline__ void mma_tf32(
    float& c0, float& c1, float& c2, float& c3,
    unsigned a0, unsigned a1, unsigned a2, unsigned a3,
    unsigned b0, unsigned b1)
{
    asm volatile(
        "mma.sync.aligned.m16n8k8.row.col.f32.tf32.tf32.f32 "
        "{%0,%1,%2,%3}, {%4,%5,%6,%7}, {%8,%9}, {%0,%1,%2,%3};\n"
        : "+f"(c0), "+f"(c1), "+f"(c2), "+f"(c3)
        : "r"(a0), "r"(a1), "r"(a2), "r"(a3), "r"(b0), "r"(b1));
}

// ---------------------------------------------------------------------------
// TF32 tensor-core GEMM NT: C[m,n] = sum_k A[m,k] * W[n,k] + bias[n]
// MODE 0: plain row-major store to C [M, 1024]
// MODE 1: fused RoPE + transpose store to C as [B,H,N,HD]
// ---------------------------------------------------------------------------
#define KPAD 36
#define CPAD 132
#define GEMM_SMEM (128 * CPAD * 4)   // 67584 B >= 2*128*KPAD*4 = 36864 B

template <int MODE>
__global__ __launch_bounds__(256) void gemm_tf32(
    const float* __restrict__ A, const float* __restrict__ W,
    const float* __restrict__ bias, float* __restrict__ C, int M,
    const float* __restrict__ sinp, const float* __restrict__ cosp)
{
    extern __shared__ unsigned smem_dyn[];
    unsigned* As = smem_dyn;
    unsigned* Ws = As + 128 * KPAD;

    const int tid  = threadIdx.x;
    const int warp = tid >> 5;
    const int lane = tid & 31;
    const int g    = lane >> 2;   // 0..7
    const int q    = lane & 3;    // 0..3
    const int wm   = warp >> 2;   // 0..1
    const int wn   = warp & 3;    // 0..3
    const int row0 = blockIdx.y * 128;
    const int col0 = blockIdx.x * 128;

    float acc[4][4][4];
    #pragma unroll
    for (int mt = 0; mt < 4; mt++)
        #pragma unroll
        for (int nt = 0; nt < 4; nt++)
            #pragma unroll
            for (int i = 0; i < 4; i++) acc[mt][nt][i] = 0.f;

    int lrow[4], lk[4];
    #pragma unroll
    for (int j = 0; j < 4; j++) {
        int idx = tid + j * 256;
        lrow[j] = idx >> 3;
        lk[j]   = (idx & 7) * 4;
    }

    const float4 z4 = make_float4(0.f, 0.f, 0.f, 0.f);
    float4 pa[4], pw[4];
    #pragma unroll
    for (int j = 0; j < 4; j++) {
        int r = row0 + lrow[j];
        pa[j] = (r < M) ? *(const float4*)(A + (long long)r * DD + lk[j]) : z4;
        pw[j] = *(const float4*)(W + (long long)(col0 + lrow[j]) * DD + lk[j]);
    }

    for (int chunk = 0; chunk < DD / 32; chunk++) {
        #pragma unroll
        for (int j = 0; j < 4; j++) {
            unsigned* as = &As[lrow[j] * KPAD + lk[j]];
            as[0] = f2tf(pa[j].x); as[1] = f2tf(pa[j].y);
            as[2] = f2tf(pa[j].z); as[3] = f2tf(pa[j].w);
            unsigned* ws = &Ws[lrow[j] * KPAD + lk[j]];
            ws[0] = f2tf(pw[j].x); ws[1] = f2tf(pw[j].y);
            ws[2] = f2tf(pw[j].z); ws[3] = f2tf(pw[j].w);
        }
        __syncthreads();

        if (chunk + 1 < DD / 32) {
            int kb = (chunk + 1) * 32;
            #pragma unroll
            for (int j = 0; j < 4; j++) {
                int r = row0 + lrow[j];
                pa[j] = (r < M) ? *(const float4*)(A + (long long)r * DD + kb + lk[j]) : z4;
                pw[j] = *(const float4*)(W + (long long)(col0 + lrow[j]) * DD + kb + lk[j]);
            }
        }

        #pragma unroll
        for (int ks = 0; ks < 4; ks++) {
            const int kc = ks * 8 + q;
            unsigned af[4][4], bf[4][2];
            #pragma unroll
            for (int mt = 0; mt < 4; mt++) {
                int base = (wm * 64 + mt * 16 + g) * KPAD + kc;
                af[mt][0] = As[base];
                af[mt][1] = As[base + 8 * KPAD];
                af[mt][2] = As[base + 4];
                af[mt][3] = As[base + 8 * KPAD + 4];
            }
            #pragma unroll
            for (int nt = 0; nt < 4; nt++) {
                int base = (wn * 32 + nt * 8 + g) * KPAD + kc;
                bf[nt][0] = Ws[base];
                bf[nt][1] = Ws[base + 4];
            }
            #pragma unroll
            for (int mt = 0; mt < 4; mt++)
                #pragma unroll
                for (int nt = 0; nt < 4; nt++)
                    mma_tf32(acc[mt][nt][0], acc[mt][nt][1],
                             acc[mt][nt][2], acc[mt][nt][3],
                             af[mt][0], af[mt][1], af[mt][2], af[mt][3],
                             bf[nt][0], bf[nt][1]);
        }
        __syncthreads();
    }

    if (MODE == 0) {
        // plain epilogue: bias + row-major store
        #pragma unroll
        for (int mt = 0; mt < 4; mt++) {
            int r0 = row0 + wm * 64 + mt * 16 + g;
            int r1 = r0 + 8;
            #pragma unroll
            for (int nt = 0; nt < 4; nt++) {
                int c = col0 + wn * 32 + nt * 8 + 2 * q;
                float bx = bias[c], by = bias[c + 1];
                if (r0 < M) {
                    float2 v = make_float2(acc[mt][nt][0] + bx, acc[mt][nt][1] + by);
                    *(float2*)(C + (long long)r0 * DD + c) = v;
                }
                if (r1 < M) {
                    float2 v = make_float2(acc[mt][nt][2] + bx, acc[mt][nt][3] + by);
                    *(float2*)(C + (long long)r1 * DD + c) = v;
                }
            }
        }
    } else {
        // fused epilogue: stage (bias applied), then RoPE + transpose store
        float* Cs = (float*)smem_dyn;   // 128 x CPAD
        #pragma unroll
        for (int mt = 0; mt < 4; mt++) {
            int lr0 = wm * 64 + mt * 16 + g;
            int lr1 = lr0 + 8;
            #pragma unroll
            for (int nt = 0; nt < 4; nt++) {
                int lc = wn * 32 + nt * 8 + 2 * q;
                float bx = bias[col0 + lc], by = bias[col0 + lc + 1];
                *(float2*)&Cs[lr0 * CPAD + lc] =
                    make_float2(acc[mt][nt][0] + bx, acc[mt][nt][1] + by);
                *(float2*)&Cs[lr1 * CPAD + lc] =
                    make_float2(acc[mt][nt][2] + bx, acc[mt][nt][3] + by);
            }
        }
        __syncthreads();

        // FIX: full 128x128 tile = 4096 float4s = 16 per thread
        // (R4 bug: only 8 iterations -> half the columns never stored)
        #pragma unroll
        for (int i = 0; i < 16; i++) {
            int idx = tid + i * 256;
            int row = idx >> 5;             // 0..127
            int c4  = (idx & 31) * 4;       // 0..124
            int R = row0 + row;
            if (R >= M) continue;
            int b = R / NN;
            int t = R - b * NN;
            int gcol = col0 + c4;
            int h = gcol >> 6;
            int d = gcol & 63;

            float4 x = *(float4*)&Cs[row * CPAD + c4];
            float4 v = x;
            if (t >= PREFIX) {
                int pos = t - PREFIX;
                float4 cc = *(const float4*)(cosp + pos * HD + d);
                float4 ss = *(const float4*)(sinp + pos * HD + d);
                float4 xo = *(float4*)&Cs[row * CPAD + (c4 ^ 32)];
                if (d < 32) { xo.x = -xo.x; xo.y = -xo.y; xo.z = -xo.z; xo.w = -xo.w; }
                v.x = x.x * cc.x + xo.x * ss.x;
                v.y = x.y * cc.y + xo.y * ss.y;
                v.z = x.z * cc.z + xo.z * ss.z;
                v.w = x.w * cc.w + xo.w * ss.w;
            }
            *(float4*)(C + (((long long)(b * HH + h)) * NN + t) * HD + d) = v;
        }
    }
}

// ---------------------------------------------------------------------------
// Tensor-core flash attention (tf32 mma, online softmax)
// Q,K: [B,H,N,HD].  V: [B,N,H*HD] (raw GEMM output).  CTX: [B,N,H*HD].
// 256 threads (8 warps), 128-query tile, 64-KV tiles, 2 CTAs/SM.
// ---------------------------------------------------------------------------
#define ST 68
#define FA_SMEM ((384 * ST) * 4 + 256 * 4)

__global__ __launch_bounds__(256, 2) void flash_attn_tc(
    const float* __restrict__ Q, const float* __restrict__ K,
    const float* __restrict__ Vy, float* __restrict__ CTX)
{
    extern __shared__ unsigned sm_u[];
    unsigned* Qs = sm_u;                    // 128 x ST
    unsigned* Ks = Qs + 128 * ST;           // 64 x ST
    unsigned* Vs = Ks + 64 * ST;            // 64 x ST  ([kv][d])
    unsigned* Ps = Vs + 64 * ST;            // 128 x ST (tf32 P / float O stage)
    float* scl  = (float*)(Ps + 128 * ST);  // 128 per-query rescale
    float* linv = scl + 128;                // 128 per-query 1/l

    const int q0 = blockIdx.x * 128;
    const int h  = blockIdx.y;
    const int b  = blockIdx.z;
    const long long baseQ = ((long long)(b * HH + h)) * NN * HD;
    const int tid  = threadIdx.x;
    const int warp = tid >> 5;
    const int lane = tid & 31;
    const int g    = lane >> 2;
    const int q    = lane & 3;
    const int sr0  = warp * 16 + g;       // S-phase rows (queries)
    const int sr1  = sr0 + 8;
    const int d0   = (warp & 3) * 16;     // O-phase d rows
    const int qb   = (warp >> 2) * 64;    // O-phase query cols

    // load Q tile (scaled by HD^-0.5)
    #pragma unroll
    for (int i = 0; i < 8; i++) {
        int idx = tid + i * 256;
        int row = idx >> 4, c4 = (idx & 15) * 4;
        int r = q0 + row;
        float4 v = (r < NN) ? *(const float4*)(Q + baseQ + (long long)r * HD + c4)
                            : make_float4(0.f, 0.f, 0.f, 0.f);
        unsigned* p = &Qs[row * ST + c4];
        p[0] = f2tf(v.x * 0.125f); p[1] = f2tf(v.y * 0.125f);
        p[2] = f2tf(v.z * 0.125f); p[3] = f2tf(v.w * 0.125f);
    }

    float m0 = -1e30f, m1 = -1e30f, l0 = 0.f, l1 = 0.f;
    float oacc[8][4];
    #pragma unroll
    for (int nt = 0; nt < 8; nt++)
        #pragma unroll
        for (int i = 0; i < 4; i++) oacc[nt][i] = 0.f;

    for (int k0 = 0; k0 < NN; k0 += 64) {
        __syncthreads();
        // load K and V tiles
        #pragma unroll
        for (int i = 0; i < 4; i++) {
            int idx = tid + i * 256;
            int j = idx >> 4, c4 = (idx & 15) * 4;
            int kv = k0 + j;
            float4 kvec, vvec;
            if (kv < NN) {
                kvec = *(const float4*)(K + baseQ + (long long)kv * HD + c4);
                vvec = *(const float4*)(Vy + ((long long)(b * NN + kv)) * DD + h * HD + c4);
            } else {
                kvec = make_float4(0.f, 0.f, 0.f, 0.f);
                vvec = kvec;
            }
            unsigned* pk = &Ks[j * ST + c4];
            pk[0] = f2tf(kvec.x); pk[1] = f2tf(kvec.y);
            pk[2] = f2tf(kvec.z); pk[3] = f2tf(kvec.w);
            unsigned* pv = &Vs[j * ST + c4];
            pv[0] = f2tf(vvec.x); pv[1] = f2tf(vvec.y);
            pv[2] = f2tf(vvec.z); pv[3] = f2tf(vvec.w);
        }
        __syncthreads();

        // S = Q @ K^T for this warp's 16 rows
        float sacc[8][4];
        #pragma unroll
        for (int nt = 0; nt < 8; nt++)
            #pragma unroll
            for (int i = 0; i < 4; i++) sacc[nt][i] = 0.f;

        #pragma unroll
        for (int ks = 0; ks < 8; ks++) {
            const int kc = ks * 8 + q;
            unsigned a0 = Qs[sr0 * ST + kc];
            unsigned a1 = Qs[sr1 * ST + kc];
            unsigned a2 = Qs[sr0 * ST + kc + 4];
            unsigned a3 = Qs[sr1 * ST + kc + 4];
            #pragma unroll
            for (int nt = 0; nt < 8; nt++) {
                unsigned b0 = Ks[(nt * 8 + g) * ST + kc];
                unsigned b1 = Ks[(nt * 8 + g) * ST + kc + 4];
                mma_tf32(sacc[nt][0], sacc[nt][1], sacc[nt][2], sacc[nt][3],
                         a0, a1, a2, a3, b0, b1);
            }
        }

        // mask out-of-range kv
        if (k0 + 64 > NN) {
            #pragma unroll
            for (int nt = 0; nt < 8; nt++) {
                int c = k0 + nt * 8 + 2 * q;
                if (c >= NN)     { sacc[nt][0] = -1e30f; sacc[nt][2] = -1e30f; }
                if (c + 1 >= NN) { sacc[nt][1] = -1e30f; sacc[nt][3] = -1e30f; }
            }
        }

        // online softmax (quad-wide rows)
        float t0 = -1e30f, t1 = -1e30f;
        #pragma unroll
        for (int nt = 0; nt < 8; nt++) {
            t0 = fmaxf(t0, fmaxf(sacc[nt][0], sacc[nt][1]));
            t1 = fmaxf(t1, fmaxf(sacc[nt][2], sacc[nt][3]));
        }
        t0 = fmaxf(t0, __shfl_xor_sync(0xffffffffu, t0, 1));
        t0 = fmaxf(t0, __shfl_xor_sync(0xffffffffu, t0, 2));
        t1 = fmaxf(t1, __shfl_xor_sync(0xffffffffu, t1, 1));
        t1 = fmaxf(t1, __shfl_xor_sync(0xffffffffu, t1, 2));
        float mn0 = fmaxf(m0, t0), mn1 = fmaxf(m1, t1);
        float sc0 = __expf(m0 - mn0), sc1 = __expf(m1 - mn1);
        m0 = mn0; m1 = mn1;

        float ls0 = 0.f, ls1 = 0.f;
        #pragma unroll
        for (int nt = 0; nt < 8; nt++) {
            float p0 = __expf(sacc[nt][0] - mn0);
            float p1 = __expf(sacc[nt][1] - mn0);
            float p2 = __expf(sacc[nt][2] - mn1);
            float p3 = __expf(sacc[nt][3] - mn1);
            ls0 += p0 + p1;
            ls1 += p2 + p3;
            uint2 w0 = make_uint2(f2tf(p0), f2tf(p1));
            uint2 w1 = make_uint2(f2tf(p2), f2tf(p3));
            *(uint2*)&Ps[sr0 * ST + nt * 8 + 2 * q] = w0;
            *(uint2*)&Ps[sr1 * ST + nt * 8 + 2 * q] = w1;
        }
        ls0 += __shfl_xor_sync(0xffffffffu, ls0, 1);
        ls0 += __shfl_xor_sync(0xffffffffu, ls0, 2);
        ls1 += __shfl_xor_sync(0xffffffffu, ls1, 1);
        ls1 += __shfl_xor_sync(0xffffffffu, ls1, 2);
        l0 = l0 * sc0 + ls0;
        l1 = l1 * sc1 + ls1;
        if (q == 0) { scl[sr0] = sc0; scl[sr1] = sc1; }
        __syncthreads();

        // rescale O accumulators by per-query factor
        #pragma unroll
        for (int nt = 0; nt < 8; nt++) {
            float s0 = scl[qb + nt * 8 + 2 * q];
            float s1 = scl[qb + nt * 8 + 2 * q + 1];
            oacc[nt][0] *= s0; oacc[nt][1] *= s1;
            oacc[nt][2] *= s0; oacc[nt][3] *= s1;
        }
        // O^T += V^T @ P^T
        #pragma unroll
        for (int ks = 0; ks < 8; ks++) {
            const int kc = ks * 8 + q;
            unsigned a0 = Vs[kc * ST + d0 + g];
            unsigned a1 = Vs[kc * ST + d0 + g + 8];
            unsigned a2 = Vs[(kc + 4) * ST + d0 + g];
            unsigned a3 = Vs[(kc + 4) * ST + d0 + g + 8];
            #pragma unroll
            for (int nt = 0; nt < 8; nt++) {
                unsigned b0 = Ps[(qb + nt * 8 + g) * ST + kc];
                unsigned b1 = Ps[(qb + nt * 8 + g) * ST + kc + 4];
                mma_tf32(oacc[nt][0], oacc[nt][1], oacc[nt][2], oacc[nt][3],
                         a0, a1, a2, a3, b0, b1);
            }
        }
    }

    // final 1/l exchange
    if (q == 0) { linv[sr0] = 1.f / l0; linv[sr1] = 1.f / l1; }
    __syncthreads();

    // stage normalized O (transpose back to [query][d]) in smem
    float* Osm = (float*)Ps;
    #pragma unroll
    for (int nt = 0; nt < 8; nt++) {
        int qc = qb + nt * 8 + 2 * q;
        float i0 = linv[qc], i1 = linv[qc + 1];
        Osm[qc * ST + d0 + g]           = oacc[nt][0] * i0;
        Osm[(qc + 1) * ST + d0 + g]     = oacc[nt][1] * i1;
        Osm[qc * ST + d0 + g + 8]       = oacc[nt][2] * i0;
        Osm[(qc + 1) * ST + d0 + g + 8] = oacc[nt][3] * i1;
    }
    __syncthreads();

    // coalesced output
    #pragma unroll
    for (int i = 0; i < 8; i++) {
        int idx = tid + i * 256;
        int row = idx >> 4, c4 = (idx & 15) * 4;
        int r = q0 + row;
        if (r < NN) {
            float4 v = *(float4*)&Osm[row * ST + c4];
            *(float4*)(CTX + ((long long)(b * NN + r)) * DD + h * HD + c4) = v;
        }
    }
}

// ---------------------------------------------------------------------------
extern "C" void kernel_launch(void* const* d_in, const int* in_sizes, int n_in,
                              void* d_out, int out_size)
{
    const float* X    = (const float*)d_in[0];
    const float* sinp = (const float*)d_in[1];
    const float* cosp = (const float*)d_in[2];
    const float* Wq   = (const float*)d_in[3];
    const float* bq   = (const float*)d_in[4];
    const float* Wk   = (const float*)d_in[5];
    const float* bk   = (const float*)d_in[6];
    const float* Wv   = (const float*)d_in[7];
    const float* bv   = (const float*)d_in[8];
    const float* Wo   = (const float*)d_in[9];
    const float* bo   = (const float*)d_in[10];
    float* OUT = (float*)d_out;

    float *Qb, *Kb, *Vb, *CTX;
    cudaGetSymbolAddress((void**)&Qb,  g_Q);
    cudaGetSymbolAddress((void**)&Kb,  g_K);
    cudaGetSymbolAddress((void**)&Vb,  g_V);
    cudaGetSymbolAddress((void**)&CTX, g_CTX);

    cudaFuncSetAttribute(gemm_tf32<0>,
                         cudaFuncAttributeMaxDynamicSharedMemorySize, GEMM_SMEM);
    cudaFuncSetAttribute(gemm_tf32<1>,
                         cudaFuncAttributeMaxDynamicSharedMemorySize, GEMM_SMEM);
    cudaFuncSetAttribute(flash_attn_tc,
                         cudaFuncAttributeMaxDynamicSharedMemorySize, FA_SMEM);

    dim3 ggrid(DD / 128, (MM + 127) / 128);
    dim3 gblk(256);

    // Q/K projections with fused RoPE+transpose -> [B,H,N,HD]
    gemm_tf32<1><<<ggrid, gblk, GEMM_SMEM>>>(X, Wq, bq, Qb, MM, sinp, cosp);
    gemm_tf32<1><<<ggrid, gblk, GEMM_SMEM>>>(X, Wk, bk, Kb, MM, sinp, cosp);
    // V projection (stays in [B,N,H*HD]; attention reads it directly)
    gemm_tf32<0><<<ggrid, gblk, GEMM_SMEM>>>(X, Wv, bv, Vb, MM, sinp, cosp);

    // tensor-core attention
    dim3 agrid((NN + 127) / 128, HH, BB);   // (9,16,16)
    flash_attn_tc<<<agrid, 256, FA_SMEM>>>(Qb, Kb, Vb, CTX);

    // output projection straight into d_out
    gemm_tf32<0><<<ggrid, gblk, GEMM_SMEM>>>(CTX, Wo, bo, OUT, MM, sinp, cosp);
}